// round 13
// baseline (speedup 1.0000x reference)
#include <cuda_runtime.h>
#include <cuda_fp16.h>
#include <stdint.h>
#include <math.h>

#define BATCH  4096
#define HIDDEN 1024
#define INPUT  512
#define NOUT   4096
#define KTOT   1536
#define BM     128
#define BN     128
#define BK     64
#define NCH    (KTOT / BK)            // 24
#define ROWB    144                   // padded smem row stride (bytes): 16B bank shift per row
#define TILE_PB (128 * ROWB)          // 18432 B per tile
#define STG_PB  (2 * TILE_PB)         // 36864 B per stage (A + B)
#define SMEM_P  (128 + 3 * STG_PB)    // 110720 B -> 2 CTAs/SM (221 KB of 228)

// ---------------- device scratch ----------------
__device__ __half g_lin[(size_t)BATCH * NOUT];   // fp16 lin scratch (32 MB)
__device__ __half g_A[(size_t)BATCH * KTOT];
__device__ __half g_B[(size_t)NOUT  * KTOT];

// ---------------- helpers ----------------
__device__ __forceinline__ uint32_t smem_u32(const void* p) {
    uint32_t a;
    asm("{ .reg .u64 t; cvta.to.shared.u64 t, %1; cvt.u32.u64 %0, t; }" : "=r"(a) : "l"(p));
    return a;
}
// 1D bulk copy global -> shared::cta with mbarrier complete_tx (plain sm_90 PTX)
#define TMA_BULK(dst, src, bytes, mbar) \
    asm volatile("cp.async.bulk.shared::cta.global.mbarrier::complete_tx::bytes " \
                 "[%0], [%1], %2, [%3];" \
                 :: "r"(dst), "l"(src), "r"(bytes), "r"(mbar) : "memory")
#define MBAR_INIT(a, c) asm volatile("mbarrier.init.shared.b64 [%0], %1;" :: "r"(a), "r"(c) : "memory")
#define MBAR_EXPECT(a, b) \
    asm volatile("mbarrier.arrive.expect_tx.shared.b64 _, [%0], %1;" :: "r"(a), "r"(b) : "memory")
#define MBAR_WAIT(a, ph) do {                                                                  \
    uint32_t _m = (uint32_t)(a); uint32_t _p = (uint32_t)(ph); uint32_t _d;                    \
    asm volatile("{\n\t.reg .pred p;\n\t"                                                      \
        "mbarrier.try_wait.parity.acquire.cta.shared::cta.b64 p, [%1], %2;\n\t"                \
        "selp.b32 %0, 1, 0, p;\n\t}" : "=r"(_d) : "r"(_m), "r"(_p) : "memory");                \
    if (!_d) {                                                                                 \
        asm volatile("{\n\t.reg .pred P1;\n\t"                                                 \
            "WAIT_LOOP_%=:\n\t"                                                                \
            "mbarrier.try_wait.parity.acquire.cta.shared::cta.b64 P1, [%0], %1, 0x989680;\n\t" \
            "@P1 bra.uni WAIT_DONE_%=;\n\t"                                                    \
            "bra.uni WAIT_LOOP_%=;\n\t"                                                        \
            "WAIT_DONE_%=:\n\t}" :: "r"(_m), "r"(_p) : "memory");                              \
    } } while (0)
#define FENCE_ASYNC() asm volatile("fence.proxy.async.shared::cta;" ::: "memory")

__device__ __forceinline__ void ldsm4(uint32_t* r, uint32_t addr) {
    asm volatile("ldmatrix.sync.aligned.m8n8.x4.shared.b16 {%0,%1,%2,%3}, [%4];"
                 : "=r"(r[0]), "=r"(r[1]), "=r"(r[2]), "=r"(r[3]) : "r"(addr));
}
__device__ __forceinline__ void mma16816(float* d, const uint32_t* a,
                                         uint32_t b0, uint32_t b1) {
    asm volatile("mma.sync.aligned.m16n8k16.row.col.f32.f16.f16.f32 "
                 "{%0,%1,%2,%3}, {%4,%5,%6,%7}, {%8,%9}, {%0,%1,%2,%3};"
                 : "+f"(d[0]), "+f"(d[1]), "+f"(d[2]), "+f"(d[3])
                 : "r"(a[0]), "r"(a[1]), "r"(a[2]), "r"(a[3]), "r"(b0), "r"(b1));
}
// padded-row smem address: row stride 144 B -> conflict-free ldmatrix, no XOR
__device__ __forceinline__ uint32_t paddr(uint32_t tile, int row, int c) {
    return tile + (uint32_t)(row * ROWB) + ((uint32_t)c << 4);
}
__device__ __forceinline__ float fsig(float x)  { return 1.0f / (1.0f + __expf(-x)); }
__device__ __forceinline__ float ftanh(float x) { return 1.0f - 2.0f / (1.0f + __expf(2.0f * x)); }
__device__ __forceinline__ void h8_to_f(uint4 u, float* f) {
    const __half2* h = (const __half2*)&u;
    float2 a;
    a = __half22float2(h[0]); f[0] = a.x; f[1] = a.y;
    a = __half22float2(h[1]); f[2] = a.x; f[3] = a.y;
    a = __half22float2(h[2]); f[4] = a.x; f[5] = a.y;
    a = __half22float2(h[3]); f[6] = a.x; f[7] = a.y;
}

// ---------------- fp16 conversion (unchanged, R12) ----------------
__global__ __launch_bounds__(256)
void lnlstm_convert(const float* __restrict__ x,  const float* __restrict__ h,
                    const float* __restrict__ wi, const float* __restrict__ wh)
{
    const int blk = blockIdx.x;
    __half* dstb = blockIdx.y ? g_B : g_A;
    const float* src;
    uint32_t row, col, dcol;
    if (blk < 2048) {
        const uint32_t e0 = (blk * 256u + threadIdx.x) * 4u;
        row  = e0 >> 9;
        col  = e0 & 511u;
        dcol = col;
        src  = blockIdx.y ? wi : x;
        src += (size_t)row * INPUT + col;
    } else {
        const uint32_t e0 = ((blk - 2048) * 256u + threadIdx.x) * 4u;
        row  = e0 >> 10;
        col  = e0 & 1023u;
        dcol = INPUT + col;
        src  = blockIdx.y ? wh : h;
        src += (size_t)row * HIDDEN + col;
    }
    const float4 v = *(const float4*)src;
    __half2 p0 = __floats2half2_rn(v.x, v.y);
    __half2 p1 = __floats2half2_rn(v.z, v.w);
    uint2 u;
    u.x = *(uint32_t*)&p0;
    u.y = *(uint32_t*)&p1;
    *(uint2*)(dstb + (size_t)row * KTOT + dcol) = u;
}

// ---------------- GEMM: bulk-copy fill, padded rows, mbarrier pipeline ----------------
// CTA 128x128, 8 warps 2(M)x4(N), warp tile 64x32, 3 stages, 2 CTAs/SM.
__global__ void __launch_bounds__(256, 2)
lnlstm_mma_gemm()
{
    extern __shared__ char smem[];
    const uint32_t sb = smem_u32(smem);     // mbars at sb+0,8,16; tiles at sb+128
    const uint32_t tb = sb + 128;
    const int tid  = threadIdx.x;
    const int wid  = tid >> 5;
    const int lane = tid & 31;
    const int m0 = blockIdx.y * BM;
    const int n0 = blockIdx.x * BN;

    // per-thread fill source: threads 0-127 -> A rows, 128-255 -> B rows
    const bool isA = tid < 128;
    const __half* srow = isA ? (g_A + (size_t)(m0 + tid) * KTOT)
                             : (g_B + (size_t)(n0 + tid - 128) * KTOT);
    const uint32_t drow = tb + (isA ? (uint32_t)(tid * ROWB)
                                    : (uint32_t)(TILE_PB + (tid - 128) * ROWB));

    // ldmatrix per-lane bases (padded-row addressing)
    const int sub = lane >> 3, r8 = lane & 7;
    const int rA  = (wid >> 2) * 64 + (sub & 1) * 8 + r8;   // + mi*16
    const int cA  = sub >> 1;                               // + ks*2
    const int rB  = (wid & 3) * 32 + (sub >> 1) * 8 + r8;   // + ng*16
    const int cB  = sub & 1;                                // + ks*2

    float acc[4][4][4];
    #pragma unroll
    for (int i = 0; i < 4; ++i)
        #pragma unroll
        for (int j = 0; j < 4; ++j)
            #pragma unroll
            for (int q = 0; q < 4; ++q) acc[i][j][q] = 0.f;

    if (tid == 0) { MBAR_INIT(sb, 1); MBAR_INIT(sb + 8, 1); MBAR_INIT(sb + 16, 1); }
    FENCE_ASYNC();
    __syncthreads();

    // prologue: fill chunks 0 and 1 (stages 0, 1)
    if (tid == 0) { MBAR_EXPECT(sb,     (uint32_t)(2 * BM * BK * 2)); }
    TMA_BULK(drow,          srow,            128u, sb);
    if (tid == 0) { MBAR_EXPECT(sb + 8, (uint32_t)(2 * BM * BK * 2)); }
    TMA_BULK(drow + STG_PB, srow + BK,       128u, sb + 8);

    uint32_t ph = 0;    // per-stage parity bits

    #pragma unroll 1
    for (int ch = 0; ch < NCH; ++ch) {
        __syncthreads();   // all warps done with stage (ch+2)%3's previous use
        if (ch + 2 < NCH) {
            const int fs = (ch + 2) % 3;
            if (tid == 0) MBAR_EXPECT(sb + fs * 8, (uint32_t)(2 * BM * BK * 2));
            TMA_BULK(drow + fs * STG_PB, srow + (size_t)(ch + 2) * BK, 128u, sb + fs * 8);
        }
        const int s = ch % 3;
        MBAR_WAIT(sb + s * 8, (ph >> s) & 1u);
        ph ^= (1u << s);

        const uint32_t tA = tb + s * STG_PB, tB = tA + TILE_PB;
        #pragma unroll
        for (int ks = 0; ks < 4; ++ks) {
            uint32_t a[4][4], b[2][4];
            #pragma unroll
            for (int mi = 0; mi < 4; ++mi)
                ldsm4(a[mi], paddr(tA, rA + mi * 16, ks * 2 + cA));
            #pragma unroll
            for (int ng = 0; ng < 2; ++ng)
                ldsm4(b[ng], paddr(tB, rB + ng * 16, ks * 2 + cB));
            #pragma unroll
            for (int mi = 0; mi < 4; ++mi) {
                #pragma unroll
                for (int ni = 0; ni < 4; ++ni) {
                    const int g = ni >> 1, o = (ni & 1) * 2;
                    mma16816(acc[mi][ni], a[mi], b[g][o], b[g][o + 1]);
                }
            }
        }
    }

    // writeback (fp16)
    const int g = lane >> 2, tq = lane & 3;
    #pragma unroll
    for (int mi = 0; mi < 4; ++mi) {
        const int row = m0 + (wid >> 2) * 64 + mi * 16 + g;
        #pragma unroll
        for (int ni = 0; ni < 4; ++ni) {
            const int col = n0 + (wid & 3) * 32 + ni * 8 + tq * 2;
            __half* p = g_lin + (size_t)row * NOUT + col;
            *(__half2*)p                      = __floats2half2_rn(acc[mi][ni][0], acc[mi][ni][1]);
            *(__half2*)(p + (size_t)8 * NOUT) = __floats2half2_rn(acc[mi][ni][2], acc[mi][ni][3]);
        }
    }
}

// ---------------- epilogue (unchanged, R12): 128 threads/row, 2 barriers ----------------
__global__ __launch_bounds__(128)
void lnlstm_epilogue(const float* __restrict__ c,
                     const float* __restrict__ lnw_h, const float* __restrict__ lnb_h,
                     const float* __restrict__ lnw_c, const float* __restrict__ lnb_c,
                     float* __restrict__ h_out, float* __restrict__ c_out)
{
    __shared__ float4 redS[4], redQ[4];
    __shared__ float2 red2[4];
    const int b = blockIdx.x;
    const int t = threadIdx.x;
    const int w = t >> 5, l = t & 31;
    const __half* rowp = g_lin + (size_t)b * NOUT;
    const int jo = t * 8;
    const float inv = 1.0f / HIDDEN;

    float f[4][8];
    float s[4], q[4];
    #pragma unroll
    for (int g = 0; g < 4; ++g) {
        h8_to_f(*(const uint4*)(rowp + g * HIDDEN + jo), f[g]);
        s[g] = 0.f; q[g] = 0.f;
        #pragma unroll
        for (int e = 0; e < 8; ++e) { s[g] += f[g][e]; q[g] += f[g][e] * f[g][e]; }
    }
    #pragma unroll
    for (int o = 16; o > 0; o >>= 1) {
        #pragma unroll
        for (int g = 0; g < 4; ++g) {
            s[g] += __shfl_xor_sync(0xffffffffu, s[g], o);
            q[g] += __shfl_xor_sync(0xffffffffu, q[g], o);
        }
    }
    if (l == 0) { redS[w] = make_float4(s[0], s[1], s[2], s[3]);
                  redQ[w] = make_float4(q[0], q[1], q[2], q[3]); }
    __syncthreads();
    float mu[4], rs[4];
    {
        float4 S = redS[0], Q = redQ[0];
        #pragma unroll
        for (int i = 1; i < 4; ++i) {
            const float4 a = redS[i], d = redQ[i];
            S.x += a.x; S.y += a.y; S.z += a.z; S.w += a.w;
            Q.x += d.x; Q.y += d.y; Q.z += d.z; Q.w += d.w;
        }
        mu[0] = S.x * inv; mu[1] = S.y * inv; mu[2] = S.z * inv; mu[3] = S.w * inv;
        rs[0] = rsqrtf(Q.x * inv - mu[0] * mu[0] + 1e-5f);
        rs[1] = rsqrtf(Q.y * inv - mu[1] * mu[1] + 1e-5f);
        rs[2] = rsqrtf(Q.z * inv - mu[2] * mu[2] + 1e-5f);
        rs[3] = rsqrtf(Q.w * inv - mu[3] * mu[3] + 1e-5f);
    }

    float lw[8], lb[8], cn[8], og[8];
    float s2 = 0.f, q2 = 0.f;
    {
        float co[8];
        *(float4*)&co[0] = ((const float4*)(c + (size_t)b * HIDDEN + jo))[0];
        *(float4*)&co[4] = ((const float4*)(c + (size_t)b * HIDDEN + jo))[1];
        float gi[8], gf[8], go[8], gc[8];
        #pragma unroll
        for (int g = 0; g < 4; ++g) {
            *(float4*)&lw[0] = ((const float4*)(lnw_h + g * HIDDEN + jo))[0];
            *(float4*)&lw[4] = ((const float4*)(lnw_h + g * HIDDEN + jo))[1];
            *(float4*)&lb[0] = ((const float4*)(lnb_h + g * HIDDEN + jo))[0];
            *(float4*)&lb[4] = ((const float4*)(lnb_h + g * HIDDEN + jo))[1];
            float* out = (g == 0) ? gi : (g == 1) ? gf : (g == 2) ? go : gc;
            #pragma unroll
            for (int e = 0; e < 8; ++e)
                out[e] = (f[g][e] - mu[g]) * rs[g] * lw[e] + lb[e];
        }
        #pragma unroll
        for (int e = 0; e < 8; ++e) {
            const float cv = fsig(gf[e] + 1.0f) * co[e] + fsig(gi[e]) * ftanh(gc[e]);
            cn[e] = cv;
            og[e] = fsig(go[e]);
            s2 += cv;
            q2 += cv * cv;
        }
    }
    #pragma unroll
    for (int o = 16; o > 0; o >>= 1) {
        s2 += __shfl_xor_sync(0xffffffffu, s2, o);
        q2 += __shfl_xor_sync(0xffffffffu, q2, o);
    }
    if (l == 0) red2[w] = make_float2(s2, q2);
    __syncthreads();
    float2 P = red2[0];
    #pragma unroll
    for (int i = 1; i < 4; ++i) { P.x += red2[i].x; P.y += red2[i].y; }
    const float mu2 = P.x * inv;
    const float rs2 = rsqrtf(P.y * inv - mu2 * mu2 + 1e-5f);

    *(float4*)&lw[0] = ((const float4*)(lnw_c + jo))[0];
    *(float4*)&lw[4] = ((const float4*)(lnw_c + jo))[1];
    *(float4*)&lb[0] = ((const float4*)(lnb_c + jo))[0];
    *(float4*)&lb[4] = ((const float4*)(lnb_c + jo))[1];
    float ho[8];
    #pragma unroll
    for (int e = 0; e < 8; ++e)
        ho[e] = og[e] * ftanh((cn[e] - mu2) * rs2 * lw[e] + lb[e]);
    float4* hp = (float4*)(h_out + (size_t)b * HIDDEN + jo);
    float4* cp = (float4*)(c_out + (size_t)b * HIDDEN + jo);
    hp[0] = *(float4*)&ho[0]; hp[1] = *(float4*)&ho[4];
    cp[0] = *(float4*)&cn[0]; cp[1] = *(float4*)&cn[4];
}

// ---------------- launch ----------------
extern "C" void kernel_launch(void* const* d_in, const int* in_sizes, int n_in,
                              void* d_out, int out_size)
{
    const float* x     = (const float*)d_in[0];
    const float* h     = (const float*)d_in[1];
    const float* c     = (const float*)d_in[2];
    const float* wih   = (const float*)d_in[3];
    const float* whh   = (const float*)d_in[4];
    const float* lnw_h = (const float*)d_in[5];
    const float* lnb_h = (const float*)d_in[6];
    const float* lnw_c = (const float*)d_in[7];
    const float* lnb_c = (const float*)d_in[8];

    float* h_out = (float*)d_out;
    float* c_out = h_out + (size_t)BATCH * HIDDEN;

    cudaFuncSetAttribute(lnlstm_mma_gemm,
                         cudaFuncAttributeMaxDynamicSharedMemorySize, SMEM_P);

    lnlstm_convert<<<dim3(6144, 2), 256>>>(x, h, wih, whh);
    lnlstm_mma_gemm<<<dim3(NOUT / BN, BATCH / BM), 256, SMEM_P>>>();
    lnlstm_epilogue<<<BATCH, 128>>>(c, lnw_h, lnb_h, lnw_c, lnb_c, h_out, c_out);
}

// round 14
// speedup vs baseline: 1.0133x; 1.0133x over previous
#include <cuda_runtime.h>
#include <cuda_fp16.h>
#include <stdint.h>
#include <math.h>

#define BATCH  4096
#define HIDDEN 1024
#define INPUT  512
#define NOUT   4096
#define KTOT   1536
#define BM     128
#define BN     128
#define BK     64
#define NCH    (KTOT / BK)          // 24
#define STAGES 3
#define TILE_B (BM * BK * 2)        // 16384 B
#define STAGE_B (2 * TILE_B)        // 32768 B
#define SMEM_B  (STAGES * STAGE_B)  // 98304 B -> 2 CTAs/SM

// ---------------- device scratch ----------------
__device__ __half g_lin[(size_t)BATCH * NOUT];   // fp16 lin scratch (32 MB)
__device__ __half g_A[(size_t)BATCH * KTOT];
__device__ __half g_B[(size_t)NOUT  * KTOT];
// per-row gate stats: [row][0..3]=sum(gate), [row][4..7]=sumsq(gate)
__device__ float  g_stat[(size_t)BATCH * 8];     // 128 KB, zeroed by convert

// ---------------- helpers ----------------
__device__ __forceinline__ uint32_t smem_u32(const void* p) {
    uint32_t a;
    asm("{ .reg .u64 t; cvta.to.shared.u64 t, %1; cvt.u32.u64 %0, t; }" : "=r"(a) : "l"(p));
    return a;
}
#define CP16(dst, src) \
    asm volatile("cp.async.cg.shared.global [%0], [%1], 16;" :: "r"(dst), "l"(src) : "memory")
#define CP_COMMIT() asm volatile("cp.async.commit_group;" ::: "memory")
#define CP_WAIT(n)  asm volatile("cp.async.wait_group %0;" :: "n"(n) : "memory")

__device__ __forceinline__ void ldsm4(uint32_t* r, uint32_t addr) {
    asm volatile("ldmatrix.sync.aligned.m8n8.x4.shared.b16 {%0,%1,%2,%3}, [%4];"
                 : "=r"(r[0]), "=r"(r[1]), "=r"(r[2]), "=r"(r[3]) : "r"(addr));
}
__device__ __forceinline__ void mma16816(float* d, const uint32_t* a,
                                         uint32_t b0, uint32_t b1) {
    asm volatile("mma.sync.aligned.m16n8k16.row.col.f32.f16.f16.f32 "
                 "{%0,%1,%2,%3}, {%4,%5,%6,%7}, {%8,%9}, {%0,%1,%2,%3};"
                 : "+f"(d[0]), "+f"(d[1]), "+f"(d[2]), "+f"(d[3])
                 : "r"(a[0]), "r"(a[1]), "r"(a[2]), "r"(a[3]), "r"(b0), "r"(b1));
}
__device__ __forceinline__ uint32_t saddr(uint32_t tile, int row, int c) {
    return tile + (uint32_t)(row * 128) + ((uint32_t)((c ^ (row & 7)) << 4));
}
__device__ __forceinline__ float fsig(float x)  { return 1.0f / (1.0f + __expf(-x)); }
__device__ __forceinline__ float ftanh(float x) { return 1.0f - 2.0f / (1.0f + __expf(2.0f * x)); }
__device__ __forceinline__ void h8_to_f(uint4 u, float* f) {
    const __half2* h = (const __half2*)&u;
    float2 a;
    a = __half22float2(h[0]); f[0] = a.x; f[1] = a.y;
    a = __half22float2(h[1]); f[2] = a.x; f[3] = a.y;
    a = __half22float2(h[2]); f[4] = a.x; f[5] = a.y;
    a = __half22float2(h[3]); f[6] = a.x; f[7] = a.y;
}

// ---------------- fp16 conversion, MLP=4, + stat zeroing ----------------
// grid (1536, 2): blocks [0,512) INPUT section, [512,1536) HIDDEN section.
// grid.y: 0 -> A (x,h), 1 -> B (wih,whh). 4 coalesced float4 loads/thread.
__global__ __launch_bounds__(256)
void lnlstm_convert(const float* __restrict__ x,  const float* __restrict__ h,
                    const float* __restrict__ wi, const float* __restrict__ wh)
{
    // zero the stats array for this launch (32 blocks x 256 threads x 4 floats)
    if (blockIdx.y == 0 && blockIdx.x < 32) {
        const uint32_t zi = (blockIdx.x * 256u + threadIdx.x) * 4u;
        *(float4*)&g_stat[zi] = make_float4(0.f, 0.f, 0.f, 0.f);
    }

    const int blk = blockIdx.x;
    __half* dstb = blockIdx.y ? g_B : g_A;
    if (blk < 512) {                                   // INPUT section (512 cols)
        const float* src = blockIdx.y ? wi : x;
        const uint32_t base = (uint32_t)blk * 1024u;   // float4 index
        #pragma unroll
        for (int i = 0; i < 4; ++i) {
            const uint32_t f4i = base + i * 256u + threadIdx.x;
            const uint32_t row = f4i >> 7;
            const uint32_t col = (f4i & 127u) * 4u;
            const float4 v = *(const float4*)(src + (size_t)f4i * 4);
            __half2 p0 = __floats2half2_rn(v.x, v.y);
            __half2 p1 = __floats2half2_rn(v.z, v.w);
            uint2 u; u.x = *(uint32_t*)&p0; u.y = *(uint32_t*)&p1;
            *(uint2*)(dstb + (size_t)row * KTOT + col) = u;
        }
    } else {                                           // HIDDEN section (1024 cols)
        const float* src = blockIdx.y ? wh : h;
        const uint32_t base = (uint32_t)(blk - 512) * 1024u;
        #pragma unroll
        for (int i = 0; i < 4; ++i) {
            const uint32_t f4i = base + i * 256u + threadIdx.x;
            const uint32_t row = f4i >> 8;
            const uint32_t col = (f4i & 255u) * 4u;
            const float4 v = *(const float4*)(src + (size_t)f4i * 4);
            __half2 p0 = __floats2half2_rn(v.x, v.y);
            __half2 p1 = __floats2half2_rn(v.z, v.w);
            uint2 u; u.x = *(uint32_t*)&p0; u.y = *(uint32_t*)&p1;
            *(uint2*)(dstb + (size_t)row * KTOT + INPUT + col) = u;
        }
    }
}

// ---------------- GEMM: g_lin = A * B^T + per-row gate stats ----------------
// CTA 128x128, 8 warps 2(M)x4(N), warp tile 64x32, 3 stages, 2 CTAs/SM.
__global__ void __launch_bounds__(256, 2)
lnlstm_mma_gemm()
{
    extern __shared__ char smem[];
    const uint32_t sb = smem_u32(smem);
    const int tid  = threadIdx.x;
    const int wid  = tid >> 5;
    const int lane = tid & 31;
    const int m0 = blockIdx.y * BM;
    const int n0 = blockIdx.x * BN;

    const int trow = tid >> 1;
    const int tc0  = (tid & 1) * 4;
    const __half* gA = g_A + (size_t)(m0 + trow) * KTOT + tc0 * 8;
    const __half* gB = g_B + (size_t)(n0 + trow) * KTOT + tc0 * 8;
    uint32_t dofs[4];
    #pragma unroll
    for (int c = 0; c < 4; ++c)
        dofs[c] = (uint32_t)(trow * 128) + ((uint32_t)(((tc0 + c) ^ (trow & 7)) << 4));

    const int sub = lane >> 3, r8 = lane & 7;
    const int rA  = (wid >> 2) * 64 + (sub & 1) * 8 + r8;
    const int cA  = sub >> 1;
    const int rB  = (wid & 3) * 32 + (sub >> 1) * 8 + r8;
    const int cB  = sub & 1;

    float acc[4][4][4];
    #pragma unroll
    for (int i = 0; i < 4; ++i)
        #pragma unroll
        for (int j = 0; j < 4; ++j)
            #pragma unroll
            for (int q = 0; q < 4; ++q) acc[i][j][q] = 0.f;

    auto load_stage = [&](int ch, int s) {
        const uint32_t base = sb + (uint32_t)s * STAGE_B;
        const size_t ke = (size_t)ch * BK;
        #pragma unroll
        for (int c = 0; c < 4; ++c) {
            CP16(base + dofs[c],          gA + ke + c * 8);
            CP16(base + TILE_B + dofs[c], gB + ke + c * 8);
        }
    };

    load_stage(0, 0); CP_COMMIT();
    load_stage(1, 1); CP_COMMIT();

    #pragma unroll 1
    for (int ch = 0; ch < NCH; ++ch) {
        CP_WAIT(1);
        __syncthreads();
        if (ch + STAGES - 1 < NCH)
            load_stage(ch + STAGES - 1, (ch + STAGES - 1) % STAGES);
        CP_COMMIT();

        const uint32_t stb = sb + (uint32_t)(ch % STAGES) * STAGE_B;
        const uint32_t tA = stb, tB = stb + TILE_B;

        #pragma unroll
        for (int ks = 0; ks < 4; ++ks) {
            uint32_t a[4][4], b[2][4];
            #pragma unroll
            for (int mi = 0; mi < 4; ++mi)
                ldsm4(a[mi], saddr(tA, rA + mi * 16, ks * 2 + cA));
            #pragma unroll
            for (int ng = 0; ng < 2; ++ng)
                ldsm4(b[ng], saddr(tB, rB + ng * 16, ks * 2 + cB));
            #pragma unroll
            for (int mi = 0; mi < 4; ++mi) {
                #pragma unroll
                for (int ni = 0; ni < 4; ++ni) {
                    const int g = ni >> 1, o = (ni & 1) * 2;
                    mma16816(acc[mi][ni], a[mi], b[g][o], b[g][o + 1]);
                }
            }
        }
    }

    // writeback (fp16) + per-row partial stats -> global atomics
    const int gate = blockIdx.x >> 3;               // which of the 4 gates this CTA's cols belong to
    const int g = lane >> 2, tq = lane & 3;
    #pragma unroll
    for (int mi = 0; mi < 4; ++mi) {
        const int row = m0 + (wid >> 2) * 64 + mi * 16 + g;
        float s0 = 0.f, q0 = 0.f, s1 = 0.f, q1 = 0.f;
        #pragma unroll
        for (int ni = 0; ni < 4; ++ni) {
            s0 += acc[mi][ni][0] + acc[mi][ni][1];
            q0 += acc[mi][ni][0] * acc[mi][ni][0] + acc[mi][ni][1] * acc[mi][ni][1];
            s1 += acc[mi][ni][2] + acc[mi][ni][3];
            q1 += acc[mi][ni][2] * acc[mi][ni][2] + acc[mi][ni][3] * acc[mi][ni][3];
            const int col = n0 + (wid & 3) * 32 + ni * 8 + tq * 2;
            __half* p = g_lin + (size_t)row * NOUT + col;
            *(__half2*)p                      = __floats2half2_rn(acc[mi][ni][0], acc[mi][ni][1]);
            *(__half2*)(p + (size_t)8 * NOUT) = __floats2half2_rn(acc[mi][ni][2], acc[mi][ni][3]);
        }
        // quad reduce (cols tq*2.. across 4 lanes = this warp's 32-col slice)
        #pragma unroll
        for (int o = 1; o <= 2; o <<= 1) {
            s0 += __shfl_xor_sync(0xffffffffu, s0, o);
            q0 += __shfl_xor_sync(0xffffffffu, q0, o);
            s1 += __shfl_xor_sync(0xffffffffu, s1, o);
            q1 += __shfl_xor_sync(0xffffffffu, q1, o);
        }
        if (tq == 0) {
            atomicAdd(&g_stat[(size_t)row * 8 + gate],           s0);
            atomicAdd(&g_stat[(size_t)row * 8 + 4 + gate],       q0);
            atomicAdd(&g_stat[(size_t)(row + 8) * 8 + gate],     s1);
            atomicAdd(&g_stat[(size_t)(row + 8) * 8 + 4 + gate], q1);
        }
    }
}

// ---------------- epilogue: stats precomputed, single pass, 1 barrier ----------------
__global__ __launch_bounds__(128)
void lnlstm_epilogue(const float* __restrict__ c,
                     const float* __restrict__ lnw_h, const float* __restrict__ lnb_h,
                     const float* __restrict__ lnw_c, const float* __restrict__ lnb_c,
                     float* __restrict__ h_out, float* __restrict__ c_out)
{
    __shared__ float2 red2[4];
    const int b = blockIdx.x;
    const int t = threadIdx.x;
    const int w = t >> 5, l = t & 31;
    const __half* rowp = g_lin + (size_t)b * NOUT;
    const int jo = t * 8;
    const float inv = 1.0f / HIDDEN;

    // gate stats: precomputed by the GEMM (fp32-exact)
    const float4 S4 = *(const float4*)&g_stat[(size_t)b * 8];
    const float4 Q4 = *(const float4*)&g_stat[(size_t)b * 8 + 4];
    float mu[4], rs[4];
    mu[0] = S4.x * inv; mu[1] = S4.y * inv; mu[2] = S4.z * inv; mu[3] = S4.w * inv;
    rs[0] = rsqrtf(Q4.x * inv - mu[0] * mu[0] + 1e-5f);
    rs[1] = rsqrtf(Q4.y * inv - mu[1] * mu[1] + 1e-5f);
    rs[2] = rsqrtf(Q4.z * inv - mu[2] * mu[2] + 1e-5f);
    rs[3] = rsqrtf(Q4.w * inv - mu[3] * mu[3] + 1e-5f);

    // single pass: load gates, normalize, activations, cell update
    float lw[8], lb[8], cn[8], og[8];
    float s2 = 0.f, q2 = 0.f;
    {
        float f[4][8];
        #pragma unroll
        for (int g = 0; g < 4; ++g)
            h8_to_f(*(const uint4*)(rowp + g * HIDDEN + jo), f[g]);
        float co[8];
        *(float4*)&co[0] = ((const float4*)(c + (size_t)b * HIDDEN + jo))[0];
        *(float4*)&co[4] = ((const float4*)(c + (size_t)b * HIDDEN + jo))[1];
        float gi[8], gf[8], go[8], gc[8];
        #pragma unroll
        for (int g = 0; g < 4; ++g) {
            *(float4*)&lw[0] = ((const float4*)(lnw_h + g * HIDDEN + jo))[0];
            *(float4*)&lw[4] = ((const float4*)(lnw_h + g * HIDDEN + jo))[1];
            *(float4*)&lb[0] = ((const float4*)(lnb_h + g * HIDDEN + jo))[0];
            *(float4*)&lb[4] = ((const float4*)(lnb_h + g * HIDDEN + jo))[1];
            float* out = (g == 0) ? gi : (g == 1) ? gf : (g == 2) ? go : gc;
            #pragma unroll
            for (int e = 0; e < 8; ++e)
                out[e] = (f[g][e] - mu[g]) * rs[g] * lw[e] + lb[e];
        }
        #pragma unroll
        for (int e = 0; e < 8; ++e) {
            const float cv = fsig(gf[e] + 1.0f) * co[e] + fsig(gi[e]) * ftanh(gc[e]);
            cn[e] = cv;
            og[e] = fsig(go[e]);
            s2 += cv;
            q2 += cv * cv;
        }
    }
    #pragma unroll
    for (int o = 16; o > 0; o >>= 1) {
        s2 += __shfl_xor_sync(0xffffffffu, s2, o);
        q2 += __shfl_xor_sync(0xffffffffu, q2, o);
    }
    if (l == 0) red2[w] = make_float2(s2, q2);
    __syncthreads();
    float2 P = red2[0];
    #pragma unroll
    for (int i = 1; i < 4; ++i) { P.x += red2[i].x; P.y += red2[i].y; }
    const float mu2 = P.x * inv;
    const float rs2 = rsqrtf(P.y * inv - mu2 * mu2 + 1e-5f);

    // cell LN + outputs
    *(float4*)&lw[0] = ((const float4*)(lnw_c + jo))[0];
    *(float4*)&lw[4] = ((const float4*)(lnw_c + jo))[1];
    *(float4*)&lb[0] = ((const float4*)(lnb_c + jo))[0];
    *(float4*)&lb[4] = ((const float4*)(lnb_c + jo))[1];
    float ho[8];
    #pragma unroll
    for (int e = 0; e < 8; ++e)
        ho[e] = og[e] * ftanh((cn[e] - mu2) * rs2 * lw[e] + lb[e]);
    float4* hp = (float4*)(h_out + (size_t)b * HIDDEN + jo);
    float4* cp = (float4*)(c_out + (size_t)b * HIDDEN + jo);
    hp[0] = *(float4*)&ho[0]; hp[1] = *(float4*)&ho[4];
    cp[0] = *(float4*)&cn[0]; cp[1] = *(float4*)&cn[4];
}

// ---------------- launch ----------------
extern "C" void kernel_launch(void* const* d_in, const int* in_sizes, int n_in,
                              void* d_out, int out_size)
{
    const float* x     = (const float*)d_in[0];
    const float* h     = (const float*)d_in[1];
    const float* c     = (const float*)d_in[2];
    const float* wih   = (const float*)d_in[3];
    const float* whh   = (const float*)d_in[4];
    const float* lnw_h = (const float*)d_in[5];
    const float* lnb_h = (const float*)d_in[6];
    const float* lnw_c = (const float*)d_in[7];
    const float* lnb_c = (const float*)d_in[8];

    float* h_out = (float*)d_out;
    float* c_out = h_out + (size_t)BATCH * HIDDEN;

    cudaFuncSetAttribute(lnlstm_mma_gemm,
                         cudaFuncAttributeMaxDynamicSharedMemorySize, SMEM_B);

    lnlstm_convert<<<dim3(1536, 2), 256>>>(x, h, wih, whh);
    lnlstm_mma_gemm<<<dim3(NOUT / BN, BATCH / BM), 256, SMEM_B>>>();
    lnlstm_epilogue<<<BATCH, 128>>>(c, lnw_h, lnb_h, lnw_c, lnb_c, h_out, c_out);
}